// round 12
// baseline (speedup 1.0000x reference)
#include <cuda_runtime.h>
#include <cstdint>

// out = concat(adj_t @ x, adj_t2 @ x), N=8192, D=256, fp32 via tf32 mma.sync.
// R12: occupancy-2 — BM=32 fused CTA (both matmuls), 256 CTAs, 2 CTAs/SM with
// INDEPENDENT barrier domains so one CTA's warps cover the other's barrier
// stalls. Warp = 32M x 64N x one matrix -> 64 acc regs, fits 128-reg cap.

constexpr int NN = 8192;
constexpr int DD = 256;
constexpr int BM = 32;
constexpr int BK = 32;
constexpr int NITER = NN / BK;            // 256
constexpr int ASTRIDE = 36;               // 36 % 32 == 4 -> conflict-free scalar A
constexpr int BSTRIDE = 264;              // 264 % 32 == 8 -> conflict-free B
constexpr int A_ELE = BM * ASTRIDE;       // 1152 floats per matrix
constexpr int B_ELE = BK * BSTRIDE;       // 8448 floats
constexpr int STG_FLT = 2 * A_ELE + B_ELE;    // 10752
constexpr int SMEM_BYTES = 2 * STG_FLT * 4;   // 86016 -> 2 CTAs/SM fit (172 KB)

__device__ float g_xt[(size_t)NN * DD];   // x pre-converted to tf32 (rna)

#define CP_ASYNC16(dst, src) \
    asm volatile("cp.async.cg.shared.global [%0], [%1], 16;" :: "r"(dst), "l"(src))

__device__ __forceinline__ uint32_t smem_u32(const void* p) {
    uint32_t a;
    asm("{ .reg .u64 t; cvta.to.shared.u64 t, %1; cvt.u32.u64 %0, t; }"
        : "=r"(a) : "l"(p));
    return a;
}

__device__ __forceinline__ void mma_tf32(float c[4], const uint32_t a[4],
                                         const uint32_t b0, const uint32_t b1) {
    asm volatile(
        "mma.sync.aligned.m16n8k8.row.col.f32.tf32.tf32.f32 "
        "{%0,%1,%2,%3}, {%4,%5,%6,%7}, {%8,%9}, {%0,%1,%2,%3};"
        : "+f"(c[0]), "+f"(c[1]), "+f"(c[2]), "+f"(c[3])
        : "r"(a[0]), "r"(a[1]), "r"(a[2]), "r"(a[3]), "r"(b0), "r"(b1));
}

__global__ void xprep(const float* __restrict__ x) {
    const int i = blockIdx.x * 256 + threadIdx.x;
    float v = x[i];
    uint32_t t;
    asm("cvt.rna.tf32.f32 %0, %1;" : "=r"(t) : "f"(v));
    g_xt[i] = __uint_as_float(t);
}

__global__ void __launch_bounds__(256, 2) h2gcn_mma(
    const float* __restrict__ adj1,
    const float* __restrict__ adj2,
    float* __restrict__ out)
{
    extern __shared__ float smf[];
    const uint32_t smb = smem_u32(smf);

    const int t    = threadIdx.x;
    const int wid  = t >> 5;
    const int lane = t & 31;
    const int m0   = blockIdx.x * BM;

    const int g   = wid >> 2;        // matrix selector (0: adj_t, 1: adj_t2)
    const int wn  = wid & 3;         // 4 warp cols (64 N each)
    const int gid = lane >> 2;
    const int tig = lane & 3;
    const int koff = g * 2;          // SMSP buddies (wid, wid+4) anti-phased

    // ---- cp.async assignments (256 threads, BK=32, BM=32) ----
    // A1/A2: 32 rows x 8 chunks = 256 each -> 1/thread/matrix; B: 2048 -> 8/thread
    const char* a1ptr; const char* a2ptr; uint32_t adst0;
    {
        int row = t >> 3;            // 0..31
        int c   = t & 7;
        a1ptr = reinterpret_cast<const char*>(adj1 + (size_t)(m0 + row) * NN) + c * 16;
        a2ptr = reinterpret_cast<const char*>(adj2 + (size_t)(m0 + row) * NN) + c * 16;
        adst0 = (uint32_t)((row * ASTRIDE + c * 4) * 4);
    }
    const char* bptr[8];
    uint32_t    bdst[8];
#pragma unroll
    for (int j = 0; j < 8; j++) {
        int id  = t + 256 * j;
        int row = id >> 6;           // k in tile (0..31)
        int c   = id & 63;
        bptr[j] = reinterpret_cast<const char*>(g_xt + (size_t)row * DD) + c * 16;
        bdst[j] = (uint32_t)((2 * A_ELE + row * BSTRIDE + c * 4) * 4);
    }

    auto load_stage = [&](int buf) {
        const uint32_t sb = smb + (uint32_t)(buf * STG_FLT * 4);
        if (t < 256) {  // always true; keeps structure simple
            CP_ASYNC16(sb + adst0, a1ptr);              a1ptr += BK * 4;
            CP_ASYNC16(sb + A_ELE * 4 + adst0, a2ptr);  a2ptr += BK * 4;
        }
#pragma unroll
        for (int j = 0; j < 8; j++) {
            CP_ASYNC16(sb + bdst[j], bptr[j]);
            bptr[j] += (size_t)BK * DD * 4;
        }
        asm volatile("cp.async.commit_group;");
    };

    float acc[2][8][4];   // [mt][nt][i]: 32M x 64N, one matrix
#pragma unroll
    for (int mt = 0; mt < 2; mt++)
#pragma unroll
        for (int nt = 0; nt < 8; nt++)
#pragma unroll
            for (int i = 0; i < 4; i++) acc[mt][nt][i] = 0.0f;

    const int ar0 = gid * ASTRIDE + tig + g * A_ELE;   // A frag base (own matrix)
    const int bc0 = wn * 64 + gid;                      // B frag column base

    load_stage(0);

    for (int it = 0; it < NITER; it++) {
        asm volatile("cp.async.wait_group 0;");
        __syncthreads();
        if (it + 1 < NITER) load_stage((it + 1) & 1);

        const float* sA = smf + (it & 1) * STG_FLT;     // + g*A_ELE folded into ar0
        const float* sB = sA + 2 * A_ELE;

#pragma unroll
        for (int ks = 0; ks < 4; ks++) {
            const int k = ((ks + koff) & 3) * 8;   // buddy anti-phase rotation
            uint32_t b0[8], b1[8];
#pragma unroll
            for (int nt = 0; nt < 8; nt++) {
                const int n = bc0 + nt * 8;
                b0[nt] = __float_as_uint(sB[(k + tig) * BSTRIDE + n]);
                b1[nt] = __float_as_uint(sB[(k + tig + 4) * BSTRIDE + n]);
            }
            uint32_t a[2][4];
#pragma unroll
            for (int mt = 0; mt < 2; mt++) {
                const int r = ar0 + mt * 16 * ASTRIDE + k;
                a[mt][0] = __float_as_uint(sA[r]);
                a[mt][1] = __float_as_uint(sA[r + 8 * ASTRIDE]);
                a[mt][2] = __float_as_uint(sA[r + 4]);
                a[mt][3] = __float_as_uint(sA[r + 8 * ASTRIDE + 4]);
            }
#pragma unroll
            for (int mt = 0; mt < 2; mt++)
#pragma unroll
                for (int nt = 0; nt < 8; nt++)
                    mma_tf32(acc[mt][nt], a[mt], b0[nt], b1[nt]);
        }
    }

    // Epilogue: out[8192, 512]; this warp's matrix at column offset g*256
    const int colbase = g * DD + wn * 64 + 2 * tig;
#pragma unroll
    for (int mt = 0; mt < 2; mt++) {
        const int row = m0 + mt * 16 + gid;
#pragma unroll
        for (int nt = 0; nt < 8; nt++) {
            float* p0 = out + (size_t)row * (2 * DD) + colbase + nt * 8;
            float* p1 = p0 + 8 * (2 * DD);
            *reinterpret_cast<float2*>(p0) = make_float2(acc[mt][nt][0], acc[mt][nt][1]);
            *reinterpret_cast<float2*>(p1) = make_float2(acc[mt][nt][2], acc[mt][nt][3]);
        }
    }
}

extern "C" void kernel_launch(void* const* d_in, const int* in_sizes, int n_in,
                              void* d_out, int out_size) {
    const float* x  = nullptr;
    const float* a1 = nullptr;
    const float* a2 = nullptr;
    for (int i = 0; i < n_in; i++) {
        if (in_sizes[i] == NN * DD)  x  = (const float*)d_in[i];
        else if (!a1)                a1 = (const float*)d_in[i];
        else                         a2 = (const float*)d_in[i];
    }

    static bool attr_set = false;
    if (!attr_set) {
        cudaFuncSetAttribute(h2gcn_mma,
                             cudaFuncAttributeMaxDynamicSharedMemorySize, SMEM_BYTES);
        attr_set = true;
    }

    xprep<<<(NN * DD) / 256, 256>>>(x);
    h2gcn_mma<<<NN / BM, 256, SMEM_BYTES>>>(a1, a2, (float*)d_out);
}

// round 13
// speedup vs baseline: 1.8315x; 1.8315x over previous
#include <cuda_runtime.h>
#include <cuda_fp16.h>
#include <cstdint>

// out = concat(adj_t @ x, adj_t2 @ x), N=8192, D=256, fp32.
// R13: fp16 m16n8k16 mma (fp16 mantissa == tf32 mantissa -> same error,
// HALF the HMMA instructions, which R5-R12 proved is the binding floor).
// x pre-converted to fp16 AND transposed (g_xh[n][k]) so B frags are
// contiguous LDS.32; A kept fp32 in smem, LDS.64 pairs + in-reg cvt.

constexpr int NN = 8192;
constexpr int DD = 256;
constexpr int BM = 64;
constexpr int BK = 64;
constexpr int NITER = NN / BK;            // 128
constexpr int ASTRIDE = 72;               // floats; 72%32==8 -> LDS.64 conflict-free
constexpr int BSH = 72;                   // halves per B row; 36 words %32==4 -> CF
constexpr int A_ELE = BM * ASTRIDE;       // 4608 floats per matrix
constexpr int B_BYTE_OFF = 2 * A_ELE * 4; // 36864 B (B region after A1+A2)
constexpr int STG_BYTES = B_BYTE_OFF + DD * BSH * 2;  // 36864 + 36864 = 73728
constexpr int SMEM_BYTES = 2 * STG_BYTES;             // 147456

__device__ __half g_xh[(size_t)DD * NN];  // x transposed: g_xh[n][k], fp16 rn

#define CP_ASYNC16(dst, src) \
    asm volatile("cp.async.cg.shared.global [%0], [%1], 16;" :: "r"(dst), "l"(src))

__device__ __forceinline__ uint32_t smem_u32(const void* p) {
    uint32_t a;
    asm("{ .reg .u64 t; cvta.to.shared.u64 t, %1; cvt.u32.u64 %0, t; }"
        : "=r"(a) : "l"(p));
    return a;
}

__device__ __forceinline__ uint32_t pack_h2(float lo, float hi) {
    uint32_t r;   // PTX cvt.f16x2: first source -> high half
    asm("cvt.rn.f16x2.f32 %0, %1, %2;" : "=r"(r) : "f"(hi), "f"(lo));
    return r;
}

__device__ __forceinline__ void mma_f16(float c[4], const uint32_t a[4],
                                        const uint32_t b0, const uint32_t b1) {
    asm volatile(
        "mma.sync.aligned.m16n8k16.row.col.f32.f16.f16.f32 "
        "{%0,%1,%2,%3}, {%4,%5,%6,%7}, {%8,%9}, {%0,%1,%2,%3};"
        : "+f"(c[0]), "+f"(c[1]), "+f"(c[2]), "+f"(c[3])
        : "r"(a[0]), "r"(a[1]), "r"(a[2]), "r"(a[3]), "r"(b0), "r"(b1));
}

// ---------------- prep: x -> fp16(rn), transposed to [DD][NN] ----------------
__global__ void xprep(const float* __restrict__ x) {
    __shared__ float tile[32][33];
    const int kb = blockIdx.x * 32;
    const int nb = blockIdx.y * 32;
    const int tx = threadIdx.x;
    const int ty = threadIdx.y;   // blockDim (32, 8)
#pragma unroll
    for (int j = 0; j < 32; j += 8)
        tile[ty + j][tx] = x[(size_t)(kb + ty + j) * DD + nb + tx];
    __syncthreads();
#pragma unroll
    for (int j = 0; j < 32; j += 8)
        g_xh[(size_t)(nb + ty + j) * NN + kb + tx] = __float2half_rn(tile[tx][ty + j]);
}

// ---------------- fused GEMM, fp16 tensor path ----------------
__global__ void __launch_bounds__(256, 1) h2gcn_mma(
    const float* __restrict__ adj1,
    const float* __restrict__ adj2,
    float* __restrict__ out)
{
    extern __shared__ float smf[];
    const uint32_t smb = smem_u32(smf);

    const int t    = threadIdx.x;
    const int wid  = t >> 5;
    const int lane = t & 31;
    const int m0   = blockIdx.x * BM;

    const int wm  = wid & 1;         // 2 warp rows (32 M each)
    const int wn  = wid >> 1;        // 4 warp cols (64 N each)
    const int gid = lane >> 2;
    const int tig = lane & 3;
    const int koff = (wid >> 2) * 2; // SMSP buddy anti-phase (4 phases, offset 2)

    // ---- cp.async assignments (256 threads, BK=64) ----
    // A1/A2: 64 rows x 16 chunks = 1024 each -> 4/thread; B: 256 rows x 8 = 2048 -> 8/thread
    const char* a1p[4]; const char* a2p[4]; uint32_t adst[4];
#pragma unroll
    for (int j = 0; j < 4; j++) {
        int id  = t + 256 * j;
        int row = id >> 4;            // 0..63
        int c   = id & 15;            // 16B chunk within 64-float row
        a1p[j] = reinterpret_cast<const char*>(adj1 + (size_t)(m0 + row) * NN) + c * 16;
        a2p[j] = reinterpret_cast<const char*>(adj2 + (size_t)(m0 + row) * NN) + c * 16;
        adst[j] = (uint32_t)(row * (ASTRIDE * 4) + c * 16);
    }
    const char* bp[8]; uint32_t bdst[8];
#pragma unroll
    for (int j = 0; j < 8; j++) {
        int id = t + 256 * j;
        int n  = id >> 3;             // 0..255
        int c  = id & 7;              // 16B chunk within 64-half row
        bp[j] = reinterpret_cast<const char*>(g_xh + (size_t)n * NN) + c * 16;
        bdst[j] = (uint32_t)(B_BYTE_OFF + n * (BSH * 2) + c * 16);
    }

    auto load_stage = [&](int buf) {
        const uint32_t sb = smb + (uint32_t)(buf * STG_BYTES);
#pragma unroll
        for (int j = 0; j < 4; j++) {
            CP_ASYNC16(sb + adst[j], a1p[j]);                 a1p[j] += BK * 4;
            CP_ASYNC16(sb + A_ELE * 4 + adst[j], a2p[j]);     a2p[j] += BK * 4;
        }
#pragma unroll
        for (int j = 0; j < 8; j++) {
            CP_ASYNC16(sb + bdst[j], bp[j]);
            bp[j] += BK * 2;          // 64 halves = 128 B forward in k
        }
        asm volatile("cp.async.commit_group;");
    };

    float acc[2][2][8][4];   // [mat][mt][nt][i]: 32M x 64N per warp, both mats
#pragma unroll
    for (int g = 0; g < 2; g++)
#pragma unroll
        for (int mt = 0; mt < 2; mt++)
#pragma unroll
            for (int nt = 0; nt < 8; nt++)
#pragma unroll
                for (int i = 0; i < 4; i++) acc[g][mt][nt][i] = 0.0f;

    const int ar0 = (wm * 32 + gid) * ASTRIDE + 2 * tig;  // A: row gid, k-pair base
    const int bn0 = wn * 64 + gid;                         // B: col base (n)

    load_stage(0);

    for (int it = 0; it < NITER; it++) {
        asm volatile("cp.async.wait_group 0;");
        __syncthreads();
        if (it + 1 < NITER) load_stage((it + 1) & 1);

        const float* sA1 = smf + ((it & 1) ? STG_BYTES / 4 : 0);
        const float* sA2 = sA1 + A_ELE;
        const __half* sBh = reinterpret_cast<const __half*>(
            reinterpret_cast<const char*>(sA1) + B_BYTE_OFF);

#pragma unroll
        for (int ks = 0; ks < 4; ks++) {
            const int k0 = ((ks + koff) & 3) * 16;   // k16 phase, buddy-rotated
            // B frags: contiguous f16x2, conflict-free LDS.32
            uint32_t b0[8], b1[8];
#pragma unroll
            for (int nt = 0; nt < 8; nt++) {
                const __half* pb = sBh + (size_t)(bn0 + nt * 8) * BSH + k0 + 2 * tig;
                b0[nt] = *reinterpret_cast<const uint32_t*>(pb);
                b1[nt] = *reinterpret_cast<const uint32_t*>(pb + 8);
            }
            // A frags: fp32 LDS.64 pairs -> cvt.rn.f16x2
            uint32_t a[2][2][4];
#pragma unroll
            for (int g = 0; g < 2; g++) {
                const float* sA = g ? sA2 : sA1;
#pragma unroll
                for (int mt = 0; mt < 2; mt++) {
                    const float* p = sA + ar0 + mt * 16 * ASTRIDE + k0;
                    float2 v0 = *reinterpret_cast<const float2*>(p);
                    float2 v1 = *reinterpret_cast<const float2*>(p + 8 * ASTRIDE);
                    float2 v2 = *reinterpret_cast<const float2*>(p + 8);
                    float2 v3 = *reinterpret_cast<const float2*>(p + 8 * ASTRIDE + 8);
                    a[g][mt][0] = pack_h2(v0.x, v0.y);
                    a[g][mt][1] = pack_h2(v1.x, v1.y);
                    a[g][mt][2] = pack_h2(v2.x, v2.y);
                    a[g][mt][3] = pack_h2(v3.x, v3.y);
                }
            }
#pragma unroll
            for (int g = 0; g < 2; g++)
#pragma unroll
                for (int mt = 0; mt < 2; mt++)
#pragma unroll
                    for (int nt = 0; nt < 8; nt++)
                        mma_f16(acc[g][mt][nt], a[g][mt], b0[nt], b1[nt]);
        }
    }

    // Epilogue: out[8192, 512]; matrix g at column offset g*256
#pragma unroll
    for (int g = 0; g < 2; g++) {
        const int colbase = g * DD + wn * 64 + 2 * tig;
#pragma unroll
        for (int mt = 0; mt < 2; mt++) {
            const int row = m0 + wm * 32 + mt * 16 + gid;
#pragma unroll
            for (int nt = 0; nt < 8; nt++) {
                float* p0 = out + (size_t)row * (2 * DD) + colbase + nt * 8;
                float* p1 = p0 + 8 * (2 * DD);
                *reinterpret_cast<float2*>(p0) = make_float2(acc[g][mt][nt][0], acc[g][mt][nt][1]);
                *reinterpret_cast<float2*>(p1) = make_float2(acc[g][mt][nt][2], acc[g][mt][nt][3]);
            }
        }
    }
}

extern "C" void kernel_launch(void* const* d_in, const int* in_sizes, int n_in,
                              void* d_out, int out_size) {
    const float* x  = nullptr;
    const float* a1 = nullptr;
    const float* a2 = nullptr;
    for (int i = 0; i < n_in; i++) {
        if (in_sizes[i] == NN * DD)  x  = (const float*)d_in[i];
        else if (!a1)                a1 = (const float*)d_in[i];
        else                         a2 = (const float*)d_in[i];
    }

    static bool attr_set = false;
    if (!attr_set) {
        cudaFuncSetAttribute(h2gcn_mma,
                             cudaFuncAttributeMaxDynamicSharedMemorySize, SMEM_BYTES);
        attr_set = true;
    }

    xprep<<<dim3(NN / 32, DD / 32), dim3(32, 8)>>>(x);
    h2gcn_mma<<<NN / BM, 256, SMEM_BYTES>>>(a1, a2, (float*)d_out);
}